// round 2
// baseline (speedup 1.0000x reference)
#include <cuda_runtime.h>
#include <math.h>

#define TOK 65536
#define LSEQ 4096
#define NB 16
#define DM 64
#define DIP 322
#define DI 128
#define DS 32
#define CD 192
#define NH 2
#define HD 64
#define NCHUNK 64
#define QC 64

__device__ float g_zx[(size_t)DIP * TOK];
__device__ float g_conv[(size_t)CD * TOK];
__device__ float g_dt[NB * NH * LSEQ];
__device__ float g_dA[NB * NH * LSEQ];
__device__ float g_w[NB * NH * LSEQ];
__device__ float g_S[(size_t)NB * NH * NCHUNK * HD * DS];
__device__ float g_h0[(size_t)NB * NH * NCHUNK * HD * DS];
__device__ float g_y[(size_t)TOK * DI];
__device__ float g_hbuf[(size_t)DM * TOK];

// ---------------- K1: in_proj GEMM ----------------
__global__ __launch_bounds__(256) void k_inproj(const float* __restrict__ Xin,
                                                const float* __restrict__ Win,
                                                int first_layer)
{
    __shared__ float Wsh[64 * 168];
    int tok = blockIdx.x * 256 + threadIdx.x;

    float hrow[64];
    if (first_layer) {
        const float4* xr = (const float4*)(Xin + (size_t)tok * DM);
        #pragma unroll
        for (int i = 0; i < 16; i++) {
            float4 v = xr[i];
            hrow[4*i+0]=v.x; hrow[4*i+1]=v.y; hrow[4*i+2]=v.z; hrow[4*i+3]=v.w;
        }
    } else {
        #pragma unroll
        for (int k = 0; k < 64; k++) hrow[k] = g_hbuf[(size_t)k * TOK + tok];
    }

    for (int stage = 0; stage < 2; stage++) {
        int c0 = stage ? 168 : 0;
        int nc = stage ? 154 : 168;
        __syncthreads();
        for (int i = threadIdx.x; i < 64 * 168; i += 256) {
            int k = i / 168, c = i - k * 168;
            Wsh[i] = (c < nc) ? Win[k * DIP + c0 + c] : 0.0f;
        }
        __syncthreads();

        int ng = stage ? 19 : 21;
        for (int g = 0; g < ng; g++) {
            float a0=0,a1=0,a2=0,a3=0,a4=0,a5=0,a6=0,a7=0;
            #pragma unroll
            for (int k = 0; k < 64; k++) {
                const float4* wp = (const float4*)&Wsh[k * 168 + g * 8];
                float4 wa = wp[0], wb = wp[1];
                float hk = hrow[k];
                a0 += hk*wa.x; a1 += hk*wa.y; a2 += hk*wa.z; a3 += hk*wa.w;
                a4 += hk*wb.x; a5 += hk*wb.y; a6 += hk*wb.z; a7 += hk*wb.w;
            }
            int cb = c0 + g * 8;
            g_zx[(size_t)(cb+0)*TOK+tok]=a0; g_zx[(size_t)(cb+1)*TOK+tok]=a1;
            g_zx[(size_t)(cb+2)*TOK+tok]=a2; g_zx[(size_t)(cb+3)*TOK+tok]=a3;
            g_zx[(size_t)(cb+4)*TOK+tok]=a4; g_zx[(size_t)(cb+5)*TOK+tok]=a5;
            g_zx[(size_t)(cb+6)*TOK+tok]=a6; g_zx[(size_t)(cb+7)*TOK+tok]=a7;
        }
        if (stage == 1) {
            #pragma unroll
            for (int j = 0; j < 2; j++) {
                float acc = 0.0f;
                #pragma unroll
                for (int k = 0; k < 64; k++) acc += hrow[k] * Wsh[k * 168 + 152 + j];
                g_zx[(size_t)(320 + j) * TOK + tok] = acc;
            }
        }
    }
}

// ---------------- K2: conv + silu + dt/dA ----------------
__global__ __launch_bounds__(256) void k_conv(const float* __restrict__ conv_w,
                                              const float* __restrict__ conv_b,
                                              const float* __restrict__ dt_bias,
                                              const float* __restrict__ A_log)
{
    __shared__ float ws[CD * 4];
    __shared__ float bs[CD];
    int b = blockIdx.y;
    int t = blockIdx.x * 256 + threadIdx.x;
    for (int i = threadIdx.x; i < CD * 4; i += 256) ws[i] = conv_w[i];
    for (int i = threadIdx.x; i < CD; i += 256) bs[i] = conv_b[i];
    __syncthreads();

    size_t tok = (size_t)b * LSEQ + t;
    for (int c = 0; c < CD; c++) {
        const float* row = g_zx + (size_t)(DI + c) * TOK + (size_t)b * LSEQ;
        float acc = bs[c];
        #pragma unroll
        for (int j = 0; j < 4; j++) {
            int tt = t - 3 + j;
            if (tt >= 0) acc += row[tt] * ws[c * 4 + j];
        }
        g_conv[(size_t)c * TOK + tok] = acc / (1.0f + __expf(-acc));
    }
    #pragma unroll
    for (int h = 0; h < NH; h++) {
        float raw = g_zx[(size_t)(320 + h) * TOK + tok] + dt_bias[h];
        float dt = (raw > 0.0f) ? (raw + log1pf(__expf(-raw))) : log1pf(__expf(raw));
        float A = -__expf(A_log[h]);
        int bh = b * NH + h;
        g_dt[bh * LSEQ + t] = dt;
        g_dA[bh * LSEQ + t] = __expf(dt * A);
    }
}

// ---------------- K3: intra-chunk scan ----------------
__global__ __launch_bounds__(256) void k_intra(const float* __restrict__ Dp)
{
    __shared__ float sx[64 * 65];
    __shared__ float sB[64 * 36];
    __shared__ float sC[64 * 36];
    __shared__ float sdt[64], sdA[64];

    int c = blockIdx.x, h = blockIdx.y, b = blockIdx.z;
    int tid = threadIdx.x;
    size_t tok0 = (size_t)b * LSEQ + c * QC;
    int bh = b * NH + h;

    for (int li = tid; li < 1024; li += 256) {
        int pp = li >> 4, t4 = (li & 15) * 4;
        float4 v = *(const float4*)(g_conv + (size_t)(h * HD + pp) * TOK + tok0 + t4);
        sx[(t4+0)*65+pp]=v.x; sx[(t4+1)*65+pp]=v.y; sx[(t4+2)*65+pp]=v.z; sx[(t4+3)*65+pp]=v.w;
    }
    for (int li = tid; li < 512; li += 256) {
        int n = li >> 4, t4 = (li & 15) * 4;
        float4 v = *(const float4*)(g_conv + (size_t)(DI + n) * TOK + tok0 + t4);
        sB[(t4+0)*36+n]=v.x; sB[(t4+1)*36+n]=v.y; sB[(t4+2)*36+n]=v.z; sB[(t4+3)*36+n]=v.w;
    }
    for (int li = tid; li < 512; li += 256) {
        int n = li >> 4, t4 = (li & 15) * 4;
        float4 v = *(const float4*)(g_conv + (size_t)(DI + DS + n) * TOK + tok0 + t4);
        sC[(t4+0)*36+n]=v.x; sC[(t4+1)*36+n]=v.y; sC[(t4+2)*36+n]=v.z; sC[(t4+3)*36+n]=v.w;
    }
    if (tid < 64) {
        sdt[tid] = g_dt[bh * LSEQ + c * QC + tid];
        sdA[tid] = g_dA[bh * LSEQ + c * QC + tid];
    }
    __syncthreads();

    int p = tid >> 2, nq = tid & 3, n0 = nq * 8;
    float h0=0,h1=0,h2=0,h3=0,h4=0,h5=0,h6=0,h7=0;
    float wrun = 1.0f;
    float dp = Dp[h];
    float* wout = g_w + bh * LSEQ + c * QC;

    for (int t = 0; t < QC; t++) {
        float dA = sdA[t], dts = sdt[t];
        float xv = sx[t * 65 + p];
        float coef = dts * xv;
        float4 b0 = *(const float4*)&sB[t * 36 + n0];
        float4 b1 = *(const float4*)&sB[t * 36 + n0 + 4];
        float4 c0 = *(const float4*)&sC[t * 36 + n0];
        float4 c1 = *(const float4*)&sC[t * 36 + n0 + 4];
        h0 = h0*dA + coef*b0.x; h1 = h1*dA + coef*b0.y;
        h2 = h2*dA + coef*b0.z; h3 = h3*dA + coef*b0.w;
        h4 = h4*dA + coef*b1.x; h5 = h5*dA + coef*b1.y;
        h6 = h6*dA + coef*b1.z; h7 = h7*dA + coef*b1.w;
        float yp = h0*c0.x + h1*c0.y + h2*c0.z + h3*c0.w
                 + h4*c1.x + h5*c1.y + h6*c1.z + h7*c1.w;
        yp += __shfl_xor_sync(0xffffffffu, yp, 1);
        yp += __shfl_xor_sync(0xffffffffu, yp, 2);
        wrun *= dA;
        if (nq == 0) g_y[(tok0 + t) * DI + h * HD + p] = yp + dp * xv;
        if (tid == 0) wout[t] = wrun;
    }
    float* Sp = g_S + ((size_t)bh * NCHUNK + c) * (HD * DS) + p * DS + n0;
    *(float4*)Sp       = make_float4(h0, h1, h2, h3);
    *(float4*)(Sp + 4) = make_float4(h4, h5, h6, h7);
}

// ---------------- K4: inter-chunk scan ----------------
__global__ __launch_bounds__(256) void k_inter()
{
    int bh = blockIdx.x;
    int tid = threadIdx.x;
    float h0=0,h1=0,h2=0,h3=0,h4=0,h5=0,h6=0,h7=0;
    size_t base = (size_t)bh * NCHUNK * (HD * DS) + tid * 8;
    for (int c = 0; c < NCHUNK; c++) {
        float* hp = g_h0 + base + (size_t)c * (HD * DS);
        *(float4*)hp       = make_float4(h0, h1, h2, h3);
        *(float4*)(hp + 4) = make_float4(h4, h5, h6, h7);
        float P = g_w[bh * LSEQ + c * QC + (QC - 1)];
        const float* Sp = g_S + base + (size_t)c * (HD * DS);
        float4 s0 = *(const float4*)Sp;
        float4 s1 = *(const float4*)(Sp + 4);
        h0 = h0*P + s0.x; h1 = h1*P + s0.y; h2 = h2*P + s0.z; h3 = h3*P + s0.w;
        h4 = h4*P + s1.x; h5 = h5*P + s1.y; h6 = h6*P + s1.z; h7 = h7*P + s1.w;
    }
}

// ---------------- K5: inter fix + gate + RMSNorm + out_proj ----------------
extern __shared__ float smem5[];
__global__ __launch_bounds__(256) void k_fused(const float* __restrict__ Wout,
                                               const float* __restrict__ norm_w,
                                               float* __restrict__ out,
                                               int last_layer)
{
    float* h0s = smem5;            // 4096   [h][p][n]
    float* Ct  = h0s + 4096;       // 2304   [t][n] stride 36
    float* zt  = Ct + 2304;        // 8448   [t][c] stride 132
    float* ut  = zt + 8448;        // 8448
    float* Wsh = ut + 8448;        // 8704   [k][d] stride 68
    float* wvs = Wsh + 8704;       // 128
    float* nws = wvs + 128;        // 128

    int c = blockIdx.x, b = blockIdx.y;
    int tid = threadIdx.x;
    size_t tok0 = (size_t)b * LSEQ + c * QC;

    for (int i = tid; i < 1024; i += 256) {
        int hh = i >> 9;
        int s4 = (i & 511) * 4;
        *(float4*)&h0s[i * 4] =
            *(const float4*)&g_h0[((size_t)(b * NH + hh) * NCHUNK + c) * (HD * DS) + s4];
    }
    for (int li = tid; li < 512; li += 256) {
        int n = li >> 4, t4 = (li & 15) * 4;
        float4 v = *(const float4*)(g_conv + (size_t)(DI + DS + n) * TOK + tok0 + t4);
        Ct[(t4+0)*36+n]=v.x; Ct[(t4+1)*36+n]=v.y; Ct[(t4+2)*36+n]=v.z; Ct[(t4+3)*36+n]=v.w;
    }
    for (int li = tid; li < 2048; li += 256) {
        int cc = li >> 4, t4 = (li & 15) * 4;
        float4 v = *(const float4*)(g_zx + (size_t)cc * TOK + tok0 + t4);
        zt[(t4+0)*132+cc]=v.x; zt[(t4+1)*132+cc]=v.y; zt[(t4+2)*132+cc]=v.z; zt[(t4+3)*132+cc]=v.w;
    }
    for (int i = tid; i < DI * DM; i += 256) {
        int k = i >> 6, d = i & 63;
        Wsh[k * 68 + d] = Wout[i];
    }
    if (tid < 128) {
        int hh = tid >> 6, tt = tid & 63;
        wvs[tid] = g_w[(b * NH + hh) * LSEQ + c * QC + tt];
        nws[tid] = norm_w[tid];
    }
    __syncthreads();

    int t = tid >> 2, q = tid & 3, p0 = q * 32;
    int hh = p0 >> 6;
    float wv = wvs[hh * 64 + t];
    const float* h0h = h0s + hh * (HD * DS);
    const float* yrow = g_y + (tok0 + t) * DI;
    float ss = 0.0f;

    for (int pi = 0; pi < 32; pi++) {
        int p = p0 + pi, ph = p & 63;
        const float4* hp  = (const float4*)(h0h + ph * DS);
        const float4* cp4 = (const float4*)(Ct + t * 36);
        float acc = 0.0f;
        #pragma unroll
        for (int n4 = 0; n4 < 8; n4++) {
            float4 hv = hp[n4], cv = cp4[n4];
            acc += hv.x*cv.x + hv.y*cv.y + hv.z*cv.z + hv.w*cv.w;
        }
        float y = yrow[p] + wv * acc;
        float z = zt[t * 132 + p];
        float u = y * (z / (1.0f + __expf(-z)));
        ss += u * u;
        ut[t * 132 + p] = u;
    }
    ss += __shfl_xor_sync(0xffffffffu, ss, 1);
    ss += __shfl_xor_sync(0xffffffffu, ss, 2);
    float rstd = rsqrtf(ss * (1.0f / 128.0f) + 1e-5f);
    for (int pi = 0; pi < 32; pi++) {
        int p = p0 + pi;
        ut[t * 132 + p] *= rstd * nws[p];
    }
    __syncthreads();

    int d0 = q * 16;
    float acc[16];
    #pragma unroll
    for (int j = 0; j < 16; j++) acc[j] = 0.0f;
    for (int k = 0; k < DI; k++) {
        float uk = ut[t * 132 + k];
        const float4* wp = (const float4*)(Wsh + k * 68 + d0);
        #pragma unroll
        for (int d4 = 0; d4 < 4; d4++) {
            float4 w = wp[d4];
            acc[d4*4+0] += uk*w.x; acc[d4*4+1] += uk*w.y;
            acc[d4*4+2] += uk*w.z; acc[d4*4+3] += uk*w.w;
        }
    }
    if (last_layer) {
        float4* op = (float4*)(out + (tok0 + t) * DM + d0);
        op[0] = make_float4(acc[0],  acc[1],  acc[2],  acc[3]);
        op[1] = make_float4(acc[4],  acc[5],  acc[6],  acc[7]);
        op[2] = make_float4(acc[8],  acc[9],  acc[10], acc[11]);
        op[3] = make_float4(acc[12], acc[13], acc[14], acc[15]);
    } else {
        #pragma unroll
        for (int d4 = 0; d4 < 4; d4++)
            *(float4*)&zt[t * 132 + d0 + d4 * 4] =
                make_float4(acc[d4*4+0], acc[d4*4+1], acc[d4*4+2], acc[d4*4+3]);
        __syncthreads();
        for (int li = tid; li < 1024; li += 256) {
            int d = li >> 4, t4 = (li & 15) * 4;
            float4 v = make_float4(zt[(t4+0)*132+d], zt[(t4+1)*132+d],
                                   zt[(t4+2)*132+d], zt[(t4+3)*132+d]);
            *(float4*)(g_hbuf + (size_t)d * TOK + tok0 + t4) = v;
        }
    }
}

extern "C" void kernel_launch(void* const* d_in, const int* in_sizes, int n_in,
                              void* d_out, int out_size)
{
    const float* x       = (const float*)d_in[0];
    const float* Win     = (const float*)d_in[1];
    const float* conv_w  = (const float*)d_in[2];
    const float* conv_b  = (const float*)d_in[3];
    const float* dt_bias = (const float*)d_in[4];
    const float* A_log   = (const float*)d_in[5];
    const float* Dp      = (const float*)d_in[6];
    const float* norm_w  = (const float*)d_in[7];
    const float* Wout    = (const float*)d_in[8];
    float* out = (float*)d_out;

    static int smem_set = 0;
    if (!smem_set) {
        cudaFuncSetAttribute(k_fused, cudaFuncAttributeMaxDynamicSharedMemorySize,
                             32256 * (int)sizeof(float));
        smem_set = 1;
    }

    for (int i = 0; i < 8; i++) {
        k_inproj<<<TOK / 256, 256>>>(x, Win + (size_t)i * DM * DIP, i == 0);
        k_conv<<<dim3(LSEQ / 256, NB), 256>>>(conv_w + (size_t)i * CD * 4,
                                              conv_b + (size_t)i * CD,
                                              dt_bias + i * NH,
                                              A_log + i * NH);
        k_intra<<<dim3(NCHUNK, NH, NB), 256>>>(Dp + i * NH);
        k_inter<<<NB * NH, 256>>>();
        k_fused<<<dim3(NCHUNK, NB), 256, 32256 * sizeof(float)>>>(
            Wout + (size_t)i * DI * DM, norm_w + (size_t)i * DI, out, i == 7);
    }
}

// round 4
// speedup vs baseline: 1.1474x; 1.1474x over previous
#include <cuda_runtime.h>
#include <math.h>

#define TOK 65536
#define LSEQ 4096
#define NB 16
#define DM 64
#define DIP 322
#define DI 128
#define DS 32
#define CD 192
#define NH 2
#define HD 64
#define NCHUNK 64
#define QC 64

typedef unsigned long long u64;

__device__ __forceinline__ u64 pk(float a, float b) {
    u64 r; asm("mov.b64 %0,{%1,%2};" : "=l"(r) : "f"(a), "f"(b)); return r;
}
__device__ __forceinline__ float2 upk(u64 v) {
    float2 r; asm("mov.b64 {%0,%1},%2;" : "=f"(r.x), "=f"(r.y) : "l"(v)); return r;
}
__device__ __forceinline__ u64 f2fma(u64 a, u64 b, u64 c) {
    u64 d; asm("fma.rn.f32x2 %0,%1,%2,%3;" : "=l"(d) : "l"(a), "l"(b), "l"(c)); return d;
}
__device__ __forceinline__ u64 f2mul(u64 a, u64 b) {
    u64 d; asm("mul.rn.f32x2 %0,%1,%2;" : "=l"(d) : "l"(a), "l"(b)); return d;
}

__device__ float g_zx[(size_t)DIP * TOK];
__device__ float g_conv[(size_t)CD * TOK];
__device__ float g_dt[NB * NH * LSEQ];
__device__ float g_dA[NB * NH * LSEQ];
__device__ float g_w[NB * NH * LSEQ];
__device__ float g_S[(size_t)NB * NH * NCHUNK * HD * DS];
__device__ float g_h0[(size_t)NB * NH * NCHUNK * HD * DS];
__device__ float g_y[(size_t)TOK * DI];
__device__ float g_hbuf[(size_t)DM * TOK];

// ---------------- K1: in_proj GEMM (f32x2) ----------------
__global__ __launch_bounds__(256) void k_inproj(const float* __restrict__ Xin,
                                                const float* __restrict__ Win,
                                                int first_layer)
{
    __shared__ __align__(16) float Wsh[64 * 168];
    int tok = blockIdx.x * 256 + threadIdx.x;

    float hrow[64];
    if (first_layer) {
        const float4* xr = (const float4*)(Xin + (size_t)tok * DM);
        #pragma unroll
        for (int i = 0; i < 16; i++) {
            float4 v = xr[i];
            hrow[4*i+0]=v.x; hrow[4*i+1]=v.y; hrow[4*i+2]=v.z; hrow[4*i+3]=v.w;
        }
    } else {
        #pragma unroll
        for (int k = 0; k < 64; k++) hrow[k] = g_hbuf[(size_t)k * TOK + tok];
    }

    for (int stage = 0; stage < 2; stage++) {
        int c0 = stage ? 168 : 0;
        int nc = stage ? 154 : 168;
        __syncthreads();
        for (int i = threadIdx.x; i < 64 * 168; i += 256) {
            int k = i / 168, c = i - k * 168;
            Wsh[i] = (c < nc) ? Win[k * DIP + c0 + c] : 0.0f;
        }
        __syncthreads();

        int ng = stage ? 19 : 21;
        for (int g = 0; g < ng; g++) {
            u64 a0 = 0, a1 = 0, a2 = 0, a3 = 0;
            #pragma unroll 16
            for (int k = 0; k < 64; k++) {
                const ulonglong2* wp = (const ulonglong2*)&Wsh[k * 168 + g * 8];
                ulonglong2 wa = wp[0], wb = wp[1];
                u64 hk2 = pk(hrow[k], hrow[k]);
                a0 = f2fma(hk2, wa.x, a0);
                a1 = f2fma(hk2, wa.y, a1);
                a2 = f2fma(hk2, wb.x, a2);
                a3 = f2fma(hk2, wb.y, a3);
            }
            float2 r0 = upk(a0), r1 = upk(a1), r2 = upk(a2), r3 = upk(a3);
            int cb = c0 + g * 8;
            g_zx[(size_t)(cb+0)*TOK+tok]=r0.x; g_zx[(size_t)(cb+1)*TOK+tok]=r0.y;
            g_zx[(size_t)(cb+2)*TOK+tok]=r1.x; g_zx[(size_t)(cb+3)*TOK+tok]=r1.y;
            g_zx[(size_t)(cb+4)*TOK+tok]=r2.x; g_zx[(size_t)(cb+5)*TOK+tok]=r2.y;
            g_zx[(size_t)(cb+6)*TOK+tok]=r3.x; g_zx[(size_t)(cb+7)*TOK+tok]=r3.y;
        }
        if (stage == 1) {
            #pragma unroll
            for (int j = 0; j < 2; j++) {
                float acc = 0.0f;
                #pragma unroll 16
                for (int k = 0; k < 64; k++) acc += hrow[k] * Wsh[k * 168 + 152 + j];
                g_zx[(size_t)(320 + j) * TOK + tok] = acc;
            }
        }
    }
}

// ---------------- K2: conv + silu + dt/dA (smem-tiled) ----------------
extern __shared__ float csm[];
__global__ __launch_bounds__(256) void k_conv(const float* __restrict__ conv_w,
                                              const float* __restrict__ conv_b,
                                              const float* __restrict__ dt_bias,
                                              const float* __restrict__ A_log)
{
    float* tile = csm;                 // [CD][67]
    float* wsm  = csm + CD * 67;       // CD*4
    float* bsm  = wsm + CD * 4;        // CD

    int b = blockIdx.y, t0 = blockIdx.x * 64;
    int tid = threadIdx.x, wid = tid >> 5, lane = tid & 31;

    for (int i = tid; i < CD * 4; i += 256) wsm[i] = conv_w[i];
    for (int i = tid; i < CD; i += 256) bsm[i] = conv_b[i];

    for (int c = wid; c < CD; c += 8) {
        const float* row = g_zx + (size_t)(DI + c) * TOK + (size_t)b * LSEQ;
        for (int j = lane; j < 67; j += 32) {
            int tt = t0 - 3 + j;
            tile[c * 67 + j] = (tt >= 0) ? row[tt] : 0.0f;
        }
    }
    __syncthreads();

    int t = tid & 63, q = tid >> 6;
    size_t tok = (size_t)b * LSEQ + t0 + t;
    for (int c = q * 48; c < q * 48 + 48; c++) {
        const float* tr = tile + c * 67 + t;
        float acc = bsm[c] + tr[0]*wsm[c*4] + tr[1]*wsm[c*4+1]
                  + tr[2]*wsm[c*4+2] + tr[3]*wsm[c*4+3];
        g_conv[(size_t)c * TOK + tok] = acc / (1.0f + __expf(-acc));
    }
    if (tid < 128) {
        int hh = tid >> 6, tt = tid & 63;
        size_t tok2 = (size_t)b * LSEQ + t0 + tt;
        float raw = g_zx[(size_t)(320 + hh) * TOK + tok2] + dt_bias[hh];
        float dt = (raw > 0.0f) ? (raw + log1pf(__expf(-raw))) : log1pf(__expf(raw));
        float A = -__expf(A_log[hh]);
        int bh = b * NH + hh;
        g_dt[bh * LSEQ + t0 + tt] = dt;
        g_dA[bh * LSEQ + t0 + tt] = __expf(dt * A);
    }
}

// ---------------- K3: intra-chunk scan (f32x2) ----------------
__global__ __launch_bounds__(256) void k_intra(const float* __restrict__ Dp)
{
    __shared__ __align__(16) float sx[64 * 65];
    __shared__ __align__(16) float sB[64 * 36];
    __shared__ __align__(16) float sC[64 * 36];
    __shared__ float sdt[64], sdA[64];

    int c = blockIdx.x, h = blockIdx.y, b = blockIdx.z;
    int tid = threadIdx.x;
    size_t tok0 = (size_t)b * LSEQ + c * QC;
    int bh = b * NH + h;

    for (int li = tid; li < 1024; li += 256) {
        int pp = li >> 4, t4 = (li & 15) * 4;
        float4 v = *(const float4*)(g_conv + (size_t)(h * HD + pp) * TOK + tok0 + t4);
        sx[(t4+0)*65+pp]=v.x; sx[(t4+1)*65+pp]=v.y; sx[(t4+2)*65+pp]=v.z; sx[(t4+3)*65+pp]=v.w;
    }
    for (int li = tid; li < 512; li += 256) {
        int n = li >> 4, t4 = (li & 15) * 4;
        float4 v = *(const float4*)(g_conv + (size_t)(DI + n) * TOK + tok0 + t4);
        sB[(t4+0)*36+n]=v.x; sB[(t4+1)*36+n]=v.y; sB[(t4+2)*36+n]=v.z; sB[(t4+3)*36+n]=v.w;
    }
    for (int li = tid; li < 512; li += 256) {
        int n = li >> 4, t4 = (li & 15) * 4;
        float4 v = *(const float4*)(g_conv + (size_t)(DI + DS + n) * TOK + tok0 + t4);
        sC[(t4+0)*36+n]=v.x; sC[(t4+1)*36+n]=v.y; sC[(t4+2)*36+n]=v.z; sC[(t4+3)*36+n]=v.w;
    }
    if (tid < 64) {
        sdt[tid] = g_dt[bh * LSEQ + c * QC + tid];
        sdA[tid] = g_dA[bh * LSEQ + c * QC + tid];
    }
    __syncthreads();

    int p = tid >> 2, nq = tid & 3, n0 = nq * 8;
    u64 H0 = 0, H1 = 0, H2 = 0, H3 = 0;
    float wrun = 1.0f;
    float dp = Dp[h];
    float* wout = g_w + bh * LSEQ + c * QC;

    for (int t = 0; t < QC; t++) {
        float dA = sdA[t], dts = sdt[t];
        float xv = sx[t * 65 + p];
        float coef = dts * xv;
        u64 dA2 = pk(dA, dA), cf2 = pk(coef, coef);
        ulonglong2 B0 = *(const ulonglong2*)&sB[t * 36 + n0];
        ulonglong2 B1 = *(const ulonglong2*)&sB[t * 36 + n0 + 4];
        ulonglong2 C0 = *(const ulonglong2*)&sC[t * 36 + n0];
        ulonglong2 C1 = *(const ulonglong2*)&sC[t * 36 + n0 + 4];
        H0 = f2fma(H0, dA2, f2mul(cf2, B0.x));
        H1 = f2fma(H1, dA2, f2mul(cf2, B0.y));
        H2 = f2fma(H2, dA2, f2mul(cf2, B1.x));
        H3 = f2fma(H3, dA2, f2mul(cf2, B1.y));
        u64 Y = f2mul(H0, C0.x);
        Y = f2fma(H1, C0.y, Y);
        Y = f2fma(H2, C1.x, Y);
        Y = f2fma(H3, C1.y, Y);
        float2 y2 = upk(Y);
        float yp = y2.x + y2.y;
        yp += __shfl_xor_sync(0xffffffffu, yp, 1);
        yp += __shfl_xor_sync(0xffffffffu, yp, 2);
        wrun *= dA;
        if (nq == 0) g_y[(tok0 + t) * DI + h * HD + p] = yp + dp * xv;
        if (tid == 0) wout[t] = wrun;
    }
    float2 h01 = upk(H0), h23 = upk(H1), h45 = upk(H2), h67 = upk(H3);
    float* Sp = g_S + ((size_t)bh * NCHUNK + c) * (HD * DS) + p * DS + n0;
    *(float4*)Sp       = make_float4(h01.x, h01.y, h23.x, h23.y);
    *(float4*)(Sp + 4) = make_float4(h45.x, h45.y, h67.x, h67.y);
}

// ---------------- K4: inter-chunk scan (smem-staged) ----------------
extern __shared__ float ism[];
__global__ __launch_bounds__(128) void k_inter()
{
    float* sS = ism;             // 64*512
    float* sP = ism + 64 * 512;  // 64
    int part = blockIdx.x, bh = blockIdx.y;
    int tid = threadIdx.x;
    int e0 = part * 512;

    for (int i = tid; i < 8192; i += 128) {
        int c = i >> 7, e4 = (i & 127) << 2;
        *(float4*)&sS[c * 512 + e4] =
            *(const float4*)&g_S[((size_t)bh * NCHUNK + c) * (HD * DS) + e0 + e4];
    }
    if (tid < 64) sP[tid] = g_w[bh * LSEQ + tid * QC + (QC - 1)];
    __syncthreads();

    int e = tid * 4;
    float4 h = make_float4(0.f, 0.f, 0.f, 0.f);
    for (int c = 0; c < NCHUNK; c++) {
        *(float4*)&g_h0[((size_t)bh * NCHUNK + c) * (HD * DS) + e0 + e] = h;
        float P = sP[c];
        float4 s = *(const float4*)&sS[c * 512 + e];
        h.x = h.x*P + s.x; h.y = h.y*P + s.y; h.z = h.z*P + s.z; h.w = h.w*P + s.w;
    }
}

// ---------------- K5: inter fix + gate + RMSNorm + out_proj (f32x2) -------------
extern __shared__ float smem5[];
__global__ __launch_bounds__(256) void k_fused(const float* __restrict__ Wout,
                                               const float* __restrict__ norm_w,
                                               float* __restrict__ out,
                                               int last_layer)
{
    float* h0s = smem5;            // 4096   [h][p][n]
    float* Ct  = h0s + 4096;       // 2304   [t][n] stride 36
    float* zt  = Ct + 2304;        // 8448   [t][c] stride 132 (z, then u in-place)
    float* Wsh = zt + 8448;        // 8704   [k][d] stride 68
    float* wvs = Wsh + 8704;       // 128
    float* nws = wvs + 128;        // 128    total 23808 floats

    int c = blockIdx.x, b = blockIdx.y;
    int tid = threadIdx.x;
    size_t tok0 = (size_t)b * LSEQ + c * QC;

    for (int i = tid; i < 1024; i += 256) {
        int hh = i >> 9;
        int s4 = (i & 511) * 4;
        *(float4*)&h0s[i * 4] =
            *(const float4*)&g_h0[((size_t)(b * NH + hh) * NCHUNK + c) * (HD * DS) + s4];
    }
    for (int li = tid; li < 512; li += 256) {
        int n = li >> 4, t4 = (li & 15) * 4;
        float4 v = *(const float4*)(g_conv + (size_t)(DI + DS + n) * TOK + tok0 + t4);
        Ct[(t4+0)*36+n]=v.x; Ct[(t4+1)*36+n]=v.y; Ct[(t4+2)*36+n]=v.z; Ct[(t4+3)*36+n]=v.w;
    }
    for (int li = tid; li < 2048; li += 256) {
        int cc = li >> 4, t4 = (li & 15) * 4;
        float4 v = *(const float4*)(g_zx + (size_t)cc * TOK + tok0 + t4);
        zt[(t4+0)*132+cc]=v.x; zt[(t4+1)*132+cc]=v.y; zt[(t4+2)*132+cc]=v.z; zt[(t4+3)*132+cc]=v.w;
    }
    for (int i = tid; i < DI * DM; i += 256) {
        int k = i >> 6, d = i & 63;
        Wsh[k * 68 + d] = Wout[i];
    }
    if (tid < 128) {
        int hh = tid >> 6, tt = tid & 63;
        wvs[tid] = g_w[(b * NH + hh) * LSEQ + c * QC + tt];
        nws[tid] = norm_w[tid];
    }
    __syncthreads();

    int t = tid >> 2, q = tid & 3, p0 = q * 32;
    int hh = p0 >> 6;
    float wv = wvs[hh * 64 + t];
    const float* h0h = h0s + hh * (HD * DS);
    const float* yrow = g_y + (tok0 + t) * DI;
    float ss = 0.0f;

    u64 cr[16];
    {
        const ulonglong2* cp = (const ulonglong2*)(Ct + t * 36);
        #pragma unroll
        for (int i = 0; i < 8; i++) { ulonglong2 v = cp[i]; cr[2*i] = v.x; cr[2*i+1] = v.y; }
    }

    for (int p4 = 0; p4 < 8; p4++) {
        float4 y4 = *(const float4*)(yrow + p0 + p4 * 4);
        #pragma unroll
        for (int pi = 0; pi < 4; pi++) {
            int p = p0 + p4 * 4 + pi;
            int ph = p & 63;
            const ulonglong2* hp = (const ulonglong2*)(h0h + ph * DS);
            u64 A = 0;
            #pragma unroll
            for (int n = 0; n < 8; n++) {
                ulonglong2 hv = hp[n];
                A = f2fma(hv.x, cr[2*n],   A);
                A = f2fma(hv.y, cr[2*n+1], A);
            }
            float2 a2 = upk(A);
            float yv = ((const float*)&y4)[pi] + wv * (a2.x + a2.y);
            float z = zt[t * 132 + p];
            float u = yv * (z / (1.0f + __expf(-z)));
            ss += u * u;
            zt[t * 132 + p] = u;   // in-place
        }
    }
    ss += __shfl_xor_sync(0xffffffffu, ss, 1);
    ss += __shfl_xor_sync(0xffffffffu, ss, 2);
    float rstd = rsqrtf(ss * (1.0f / 128.0f) + 1e-5f);
    for (int pi = 0; pi < 32; pi++) {
        int p = p0 + pi;
        zt[t * 132 + p] *= rstd * nws[p];
    }
    __syncthreads();

    int d0 = q * 16;
    u64 acc[8];
    #pragma unroll
    for (int j = 0; j < 8; j++) acc[j] = 0;
    for (int k = 0; k < DI; k++) {
        float uk = zt[t * 132 + k];
        u64 uk2 = pk(uk, uk);
        const ulonglong2* wp = (const ulonglong2*)(Wsh + k * 68 + d0);
        ulonglong2 w0 = wp[0], w1 = wp[1], w2 = wp[2], w3 = wp[3];
        acc[0] = f2fma(uk2, w0.x, acc[0]); acc[1] = f2fma(uk2, w0.y, acc[1]);
        acc[2] = f2fma(uk2, w1.x, acc[2]); acc[3] = f2fma(uk2, w1.y, acc[3]);
        acc[4] = f2fma(uk2, w2.x, acc[4]); acc[5] = f2fma(uk2, w2.y, acc[5]);
        acc[6] = f2fma(uk2, w3.x, acc[6]); acc[7] = f2fma(uk2, w3.y, acc[7]);
    }
    float r[16];
    #pragma unroll
    for (int j = 0; j < 8; j++) { float2 v = upk(acc[j]); r[2*j] = v.x; r[2*j+1] = v.y; }

    if (last_layer) {
        float4* op = (float4*)(out + (tok0 + t) * DM + d0);
        op[0] = make_float4(r[0],  r[1],  r[2],  r[3]);
        op[1] = make_float4(r[4],  r[5],  r[6],  r[7]);
        op[2] = make_float4(r[8],  r[9],  r[10], r[11]);
        op[3] = make_float4(r[12], r[13], r[14], r[15]);
    } else {
        __syncthreads();
        #pragma unroll
        for (int d4 = 0; d4 < 4; d4++)
            *(float4*)&zt[t * 132 + d0 + d4 * 4] =
                make_float4(r[d4*4+0], r[d4*4+1], r[d4*4+2], r[d4*4+3]);
        __syncthreads();
        for (int li = tid; li < 1024; li += 256) {
            int d = li >> 4, t4 = (li & 15) * 4;
            float4 v = make_float4(zt[(t4+0)*132+d], zt[(t4+1)*132+d],
                                   zt[(t4+2)*132+d], zt[(t4+3)*132+d]);
            *(float4*)(g_hbuf + (size_t)d * TOK + tok0 + t4) = v;
        }
    }
}

extern "C" void kernel_launch(void* const* d_in, const int* in_sizes, int n_in,
                              void* d_out, int out_size)
{
    const float* x       = (const float*)d_in[0];
    const float* Win     = (const float*)d_in[1];
    const float* conv_w  = (const float*)d_in[2];
    const float* conv_b  = (const float*)d_in[3];
    const float* dt_bias = (const float*)d_in[4];
    const float* A_log   = (const float*)d_in[5];
    const float* Dp      = (const float*)d_in[6];
    const float* norm_w  = (const float*)d_in[7];
    const float* Wout    = (const float*)d_in[8];
    float* out = (float*)d_out;

    const int SM_FUSED = 23808 * 4;
    const int SM_CONV  = (CD * 67 + CD * 4 + CD) * 4;
    const int SM_INTER = (64 * 512 + 64) * 4;

    static int smem_set = 0;
    if (!smem_set) {
        cudaFuncSetAttribute(k_fused, cudaFuncAttributeMaxDynamicSharedMemorySize, SM_FUSED);
        cudaFuncSetAttribute(k_conv,  cudaFuncAttributeMaxDynamicSharedMemorySize, SM_CONV);
        cudaFuncSetAttribute(k_inter, cudaFuncAttributeMaxDynamicSharedMemorySize, SM_INTER);
        smem_set = 1;
    }

    for (int i = 0; i < 8; i++) {
        k_inproj<<<TOK / 256, 256>>>(x, Win + (size_t)i * DM * DIP, i == 0);
        k_conv<<<dim3(LSEQ / 64, NB), 256, SM_CONV>>>(conv_w + (size_t)i * CD * 4,
                                                      conv_b + (size_t)i * CD,
                                                      dt_bias + i * NH,
                                                      A_log + i * NH);
        k_intra<<<dim3(NCHUNK, NH, NB), 256>>>(Dp + i * NH);
        k_inter<<<dim3(4, NB * NH), 128, SM_INTER>>>();
        k_fused<<<dim3(NCHUNK, NB), 256, SM_FUSED>>>(
            Wout + (size_t)i * DI * DM, norm_w + (size_t)i * DI, out, i == 7);
    }
}